// round 1
// baseline (speedup 1.0000x reference)
#include <cuda_runtime.h>
#include <cstdint>

// Problem constants (fixed shapes)
constexpr int B_ = 32, N_ = 128, K_ = 16, F_ = 256, D_ = 256;
constexpr int ATOMS = 4;           // (b,n) atoms per CTA
constexpr int THREADS = 256;       // thread d owns output feature d
constexpr int TF = 32;             // f-dimension tile
constexpr int NSTEPS = F_ / TF;    // 8
constexpr int WSTRIDE = 36;        // padded tile row stride (floats) -> conflict-free float4 reads
constexpr int WTILE = D_ * WSTRIDE; // 9216 floats per W tile buffer

// Shared memory layout (in floats)
constexpr int OFF_NB  = 0;                         // ATOMS*K*F = 16384
constexpr int OFF_X   = OFF_NB  + ATOMS * K_ * F_; // 16384 ; size ATOMS*F = 1024
constexpr int OFF_WN  = OFF_X   + ATOMS * F_;      // 17408 ; 2*WTILE
constexpr int OFF_WA  = OFF_WN  + 2 * WTILE;       // 35840 ; 2*WTILE
constexpr int OFF_SMK = OFF_WA  + 2 * WTILE;       // 54272 ; ATOMS*K = 64
constexpr int OFF_AMK = OFF_SMK + ATOMS * K_;      // 54336 ; 64
constexpr int OFF_RED = OFF_AMK + ATOMS * K_;      // 54400 ; 8 warps * 16 k = 128
constexpr int OFF_LN  = OFF_RED + 128;             // 54528 ; 16
constexpr int SMEM_FLOATS = OFF_LN + 16;           // 54544 floats = 218176 B

__device__ __forceinline__ uint32_t s2u(const void* p) {
    return static_cast<uint32_t>(__cvta_generic_to_shared(p));
}
__device__ __forceinline__ void cp16(uint32_t dst, const void* src) {
    asm volatile("cp.async.cg.shared.global [%0], [%1], 16;\n" :: "r"(dst), "l"(src));
}

__device__ __forceinline__ void load_W_tiles(float* s, int tid, int stage, int f0,
                                             const float* __restrict__ Wn,
                                             const float* __restrict__ Wa) {
    uint32_t dWn = s2u(s + OFF_WN + stage * WTILE);
    uint32_t dWa = s2u(s + OFF_WA + stage * WTILE);
#pragma unroll
    for (int i = 0; i < 8; i++) {
        int idx = tid + i * THREADS;     // 0..2047 (2048 float4 per 256x32 tile)
        int row = idx >> 3;              // output feature d
        int c4  = idx & 7;               // float4 column within tile
        uint32_t doff = (uint32_t)(row * WSTRIDE + c4 * 4) * 4u;
        cp16(dWn + doff, Wn + row * F_ + f0 + c4 * 4);
        cp16(dWa + doff, Wa + row * F_ + f0 + c4 * 4);
    }
}

__global__ void __launch_bounds__(THREADS, 1)
gnn_atom_aggregate_kernel(const float* __restrict__ atom_feat,
                          const float* __restrict__ nbr_feat,
                          const float* __restrict__ smask,
                          const float* __restrict__ amask,
                          const float* __restrict__ Wa,
                          const float* __restrict__ ba,
                          const float* __restrict__ Wn,
                          const float* __restrict__ bn,
                          const float* __restrict__ wal,
                          const float* __restrict__ bal,
                          const float* __restrict__ gam,
                          const float* __restrict__ bet,
                          float* __restrict__ out)
{
    extern __shared__ float s[];
    const int tid = threadIdx.x;   // == output feature d
    const int blk = blockIdx.x;    // group of ATOMS consecutive (b,n) atoms

    // ---- prologue: async-load neighbor block, atom rows, masks (all contiguous) ----
    {
        const float* nb_src = nbr_feat + (size_t)blk * (ATOMS * K_ * F_);
        uint32_t nb_dst = s2u(s + OFF_NB);
#pragma unroll
        for (int i = 0; i < 16; i++) {
            int idx4 = tid + i * THREADS;
            cp16(nb_dst + idx4 * 16, nb_src + idx4 * 4);
        }
        cp16(s2u(s + OFF_X) + tid * 16, atom_feat + (size_t)blk * (ATOMS * F_) + tid * 4);
        if (tid < 16)
            cp16(s2u(s + OFF_SMK) + tid * 16, smask + blk * (ATOMS * K_) + tid * 4);
        else if (tid < 32)
            cp16(s2u(s + OFF_AMK) + (tid - 16) * 16, amask + blk * (ATOMS * K_) + (tid - 16) * 4);
    }
    // stage-0 W tiles in the same group
    load_W_tiles(s, tid, 0, 0, Wn, Wa);
    asm volatile("cp.async.commit_group;\n");

    // per-thread constants (overlap with async loads)
    const float ba_d  = ba[tid];
    const float bn_d  = bn[tid];
    const float wal_d = wal[tid & 63];
    const float bal_s = bal[0];
    const float g_d   = gam[tid];
    const float be_d  = bet[tid];

    float acc[ATOMS][K_];
    float accA[ATOMS];
#pragma unroll
    for (int a = 0; a < ATOMS; a++) {
        accA[a] = 0.f;
#pragma unroll
        for (int k = 0; k < K_; k++) acc[a][k] = 0.f;
    }

    // ---- main GEMM loop: double-buffered W tiles via cp.async ----
    int buf = 0;
    for (int st = 0; st < NSTEPS; st++) {
        if (st + 1 < NSTEPS) {
            load_W_tiles(s, tid, buf ^ 1, (st + 1) * TF, Wn, Wa);
            asm volatile("cp.async.commit_group;\n");
            asm volatile("cp.async.wait_group 1;\n");
        } else {
            asm volatile("cp.async.wait_group 0;\n");
        }
        __syncthreads();

        const float* wn_p = s + OFF_WN + buf * WTILE + tid * WSTRIDE;
        const float* wa_p = s + OFF_WA + buf * WTILE + tid * WSTRIDE;
        const float* nb_p = s + OFF_NB + st * TF;
        const float* x_p  = s + OFF_X  + st * TF;

#pragma unroll 2
        for (int fl = 0; fl < TF; fl += 4) {
            float4 w  = *(const float4*)(wn_p + fl);
            float4 wv = *(const float4*)(wa_p + fl);
#pragma unroll
            for (int a = 0; a < ATOMS; a++) {
                float4 xv = *(const float4*)(x_p + a * F_ + fl);
                accA[a] = fmaf(wv.x, xv.x, fmaf(wv.y, xv.y,
                          fmaf(wv.z, xv.z, fmaf(wv.w, xv.w, accA[a]))));
#pragma unroll
                for (int k = 0; k < K_; k++) {
                    float4 v = *(const float4*)(nb_p + (a * K_ + k) * F_ + fl);
                    acc[a][k] = fmaf(w.x, v.x, fmaf(w.y, v.y,
                                fmaf(w.z, v.z, fmaf(w.w, v.w, acc[a][k]))));
                }
            }
        }
        __syncthreads();   // all reads of 'buf' done before it is refilled next iter
        buf ^= 1;
    }

    // ---- epilogue per atom: score -> softmax -> ctx -> LayerNorm ----
    const int lane = tid & 31;
    const int wrp  = tid >> 5;
    const int h    = tid >> 6;          // head of feature d
    float* s_red = s + OFF_RED;
    float* s_ln  = s + OFF_LN;
    const float* s_smk = s + OFF_SMK;
    const float* s_amk = s + OFF_AMK;

#pragma unroll
    for (int a = 0; a < ATOMS; a++) {
        float afv = accA[a] + ba_d;
        float nf[K_];
        float p[K_];
#pragma unroll
        for (int k = 0; k < K_; k++) {
            nf[k] = acc[a][k] + bn_d;
            float t = afv + nf[k];
            t = (t > 0.f) ? t : 0.2f * t;        // leaky_relu
            p[k] = t * wal_d;                     // partial of score[k, h]
        }
        // butterfly-reduce the 16 partial scores across the warp (32 features)
#pragma unroll
        for (int off = 16; off; off >>= 1) {
#pragma unroll
            for (int k = 0; k < K_; k++)
                p[k] += __shfl_xor_sync(0xffffffffu, p[k], off);
        }
        if (lane == 0) {
#pragma unroll
            for (int k = 0; k < K_; k++) s_red[wrp * K_ + k] = p[k];
        }
        __syncthreads();

        // each thread rebuilds the 16 scores of its own head h (warps 2h, 2h+1)
        float sc[K_];
        float mx = -3.4e38f;
#pragma unroll
        for (int k = 0; k < K_; k++) {
            sc[k] = s_red[(2 * h) * K_ + k] + s_red[(2 * h + 1) * K_ + k]
                  + bal_s + s_smk[a * K_ + k];
            mx = fmaxf(mx, sc[k]);
        }
        float ssum = 0.f;
#pragma unroll
        for (int k = 0; k < K_; k++) { sc[k] = __expf(sc[k] - mx); ssum += sc[k]; }
        float inv = 1.f / ssum;
        float ctx = 0.f;
#pragma unroll
        for (int k = 0; k < K_; k++)
            ctx = fmaf(sc[k] * inv * s_amk[a * K_ + k], nf[k], ctx);

        // LayerNorm over 256 features (block reduce of sum, sumsq)
        float s1 = ctx, s2 = ctx * ctx;
#pragma unroll
        for (int off = 16; off; off >>= 1) {
            s1 += __shfl_xor_sync(0xffffffffu, s1, off);
            s2 += __shfl_xor_sync(0xffffffffu, s2, off);
        }
        if (lane == 0) { s_ln[wrp] = s1; s_ln[8 + wrp] = s2; }
        __syncthreads();
        float S1 = 0.f, S2 = 0.f;
#pragma unroll
        for (int w = 0; w < 8; w++) { S1 += s_ln[w]; S2 += s_ln[8 + w]; }
        float mu  = S1 * (1.f / 256.f);
        float var = S2 * (1.f / 256.f) - mu * mu;
        float o = (ctx - mu) * rsqrtf(var + 1e-5f) * g_d + be_d;
        out[(size_t)(blk * ATOMS + a) * D_ + tid] = o;
        __syncthreads();   // s_red/s_ln reused by next atom
    }
}

extern "C" void kernel_launch(void* const* d_in, const int* in_sizes, int n_in,
                              void* d_out, int out_size)
{
    const float* atom_feat = (const float*)d_in[0];
    const float* nbr_feat  = (const float*)d_in[1];
    const float* smask     = (const float*)d_in[2];
    const float* amask     = (const float*)d_in[3];
    const float* Wa        = (const float*)d_in[4];
    const float* ba        = (const float*)d_in[5];
    const float* Wn        = (const float*)d_in[6];
    const float* bn        = (const float*)d_in[7];
    const float* wal       = (const float*)d_in[8];
    const float* bal       = (const float*)d_in[9];
    const float* gam       = (const float*)d_in[10];
    const float* bet       = (const float*)d_in[11];
    float* out = (float*)d_out;

    cudaFuncSetAttribute(gnn_atom_aggregate_kernel,
                         cudaFuncAttributeMaxDynamicSharedMemorySize,
                         SMEM_FLOATS * (int)sizeof(float));

    gnn_atom_aggregate_kernel<<<(B_ * N_) / ATOMS, THREADS,
                                SMEM_FLOATS * sizeof(float)>>>(
        atom_feat, nbr_feat, smask, amask, Wa, ba, Wn, bn, wal, bal, gam, bet, out);
}

// round 2
// speedup vs baseline: 1.8208x; 1.8208x over previous
#include <cuda_runtime.h>
#include <cstdint>

// Fixed problem shapes
constexpr int B_ = 32, N_ = 128, K_ = 16, F_ = 256, D_ = 256;
constexpr int ATOMS = 8;                 // atoms per CTA
constexpr int ROWS = ATOMS * K_;         // 128 GEMM rows (atom*16 + k)
constexpr int THREADS = 512;             // 16 warps
constexpr int TF = 16;                   // F-tile per stage
constexpr int NST = F_ / TF;             // 16 stages
constexpr int PAD = 268;                 // padded row stride (floats) -> conflict-free frags

// shared memory layout (floats)
constexpr int OFF_NB  = 0;                          // 128 x 268  (nb tf32, later reused as nf)
constexpr int OFF_WN  = OFF_NB + ROWS * PAD;        // 2 x 16 x 268 (tf32 Wn tiles, [f][d])
constexpr int OFF_WA  = OFF_WN + 2 * TF * PAD;      // 2 x 16 x 268 (fp32 Wa tiles, [f][d])
constexpr int OFF_X   = OFF_WA + 2 * TF * PAD;      // 8 x 256 fp32 atom features
constexpr int OFF_SM  = OFF_X + ATOMS * F_;         // 128 softmax mask
constexpr int OFF_AM  = OFF_SM + ROWS;              // 128 attend mask
constexpr int OFF_RED = OFF_AM + ROWS;              // 2 halves x 8 warps x 16
constexpr int OFF_LN  = OFF_RED + 2 * 8 * 16;       // 2 halves x 16
constexpr int SMEM_FL = OFF_LN + 32;
// = 54048 floats = 216192 bytes

__device__ __forceinline__ float to_tf32(float x) {
    float y;
    asm("cvt.rna.tf32.f32 %0, %1;" : "=f"(y) : "f"(x));
    return y;
}

__device__ __forceinline__ void mma_tf32(float c[4], uint32_t a0, uint32_t a1,
                                         uint32_t a2, uint32_t a3,
                                         uint32_t b0, uint32_t b1) {
    asm volatile(
        "mma.sync.aligned.m16n8k8.row.col.f32.tf32.tf32.f32 "
        "{%0,%1,%2,%3},{%4,%5,%6,%7},{%8,%9},{%0,%1,%2,%3};"
        : "+f"(c[0]), "+f"(c[1]), "+f"(c[2]), "+f"(c[3])
        : "r"(a0), "r"(a1), "r"(a2), "r"(a3), "r"(b0), "r"(b1));
}

__global__ void __launch_bounds__(THREADS, 1)
gnn_atom_aggregate_kernel(const float* __restrict__ atom_feat,
                          const float* __restrict__ nbr_feat,
                          const float* __restrict__ smask,
                          const float* __restrict__ amask,
                          const float* __restrict__ Wa,
                          const float* __restrict__ ba,
                          const float* __restrict__ Wn,
                          const float* __restrict__ bn,
                          const float* __restrict__ wal,
                          const float* __restrict__ bal,
                          const float* __restrict__ gam,
                          const float* __restrict__ bet,
                          float* __restrict__ out)
{
    extern __shared__ float s[];
    const int tid  = threadIdx.x;
    const int blk  = blockIdx.x;
    const int lane = tid & 31;
    const int w    = tid >> 5;

    // ---- prologue: nb (tf32-converted), x (fp32), masks into smem ----
    {
        const float* nb_src = nbr_feat + (size_t)blk * ROWS * F_;
#pragma unroll
        for (int i = 0; i < 16; i++) {
            int g   = tid + i * THREADS;     // float4 index, 8192 total
            int row = g >> 6;
            int c4  = g & 63;
            float4 v = *(const float4*)(nb_src + (size_t)g * 4);
            float4 t = make_float4(to_tf32(v.x), to_tf32(v.y), to_tf32(v.z), to_tf32(v.w));
            *(float4*)(s + OFF_NB + row * PAD + c4 * 4) = t;
        }
        float4 xv = *(const float4*)(atom_feat + (size_t)blk * ATOMS * F_ + tid * 4);
        *(float4*)(s + OFF_X + tid * 4) = xv;
        if (tid < 32)
            ((float4*)(s + OFF_SM))[tid] = ((const float4*)(smask + blk * ROWS))[tid];
        else if (tid < 64)
            ((float4*)(s + OFF_AM))[tid - 32] = ((const float4*)(amask + blk * ROWS))[tid - 32];
    }

    // W prefetch registers: thread covers d = tid>>2 and d+128, f-chunk c = tid&3
    const int gd = tid >> 2;
    const int gc = tid & 3;
    float4 rn0, rn1, ra0, ra1;
    {
        const float* pn = Wn + (size_t)gd * F_ + gc * 4;
        const float* pa = Wa + (size_t)gd * F_ + gc * 4;
        rn0 = *(const float4*)(pn);
        rn1 = *(const float4*)(pn + 128 * F_);
        ra0 = *(const float4*)(pa);
        ra1 = *(const float4*)(pa + 128 * F_);
    }

    float acc[16][4];
#pragma unroll
    for (int j = 0; j < 16; j++) {
        acc[j][0] = 0.f; acc[j][1] = 0.f; acc[j][2] = 0.f; acc[j][3] = 0.f;
    }
    float accA[4] = {0.f, 0.f, 0.f, 0.f};

    const int rg = w & 7;       // row group (16 rows)
    const int ch = w >> 3;      // column half (128 cols)
    const int ah = tid >> 8;    // atom half for af path
    const int dd = tid & 255;   // output feature for af/epilogue

    // ---- main loop over F stages ----
    for (int st = 0; st < NST; st++) {
        const int p = st & 1;
        float* wn = s + OFF_WN + p * TF * PAD;
        float* wa = s + OFF_WA + p * TF * PAD;

        // store prefetched W tile (transpose to [f][d]; Wn gets tf32 cvt)
#pragma unroll
        for (int j = 0; j < 4; j++) {
            int fl = gc * 4 + j;
            wn[fl * PAD + gd]       = to_tf32(((const float*)&rn0)[j]);
            wn[fl * PAD + gd + 128] = to_tf32(((const float*)&rn1)[j]);
            wa[fl * PAD + gd]       = ((const float*)&ra0)[j];
            wa[fl * PAD + gd + 128] = ((const float*)&ra1)[j];
        }
        if (st + 1 < NST) {
            const float* pn = Wn + (size_t)gd * F_ + (st + 1) * TF + gc * 4;
            const float* pa = Wa + (size_t)gd * F_ + (st + 1) * TF + gc * 4;
            rn0 = *(const float4*)(pn);
            rn1 = *(const float4*)(pn + 128 * F_);
            ra0 = *(const float4*)(pa);
            ra1 = *(const float4*)(pa + 128 * F_);
        }
        __syncthreads();

        // tensor-core GEMM: 2 k8-steps per stage
        const float* nbp = s + OFF_NB;
#pragma unroll
        for (int kk = 0; kk < 2; kk++) {
            const int fc = st * TF + kk * 8 + (lane & 3);
            const int r0 = rg * 16 + (lane >> 2);
            uint32_t a0 = __float_as_uint(nbp[r0 * PAD + fc]);
            uint32_t a1 = __float_as_uint(nbp[(r0 + 8) * PAD + fc]);
            uint32_t a2 = __float_as_uint(nbp[r0 * PAD + fc + 4]);
            uint32_t a3 = __float_as_uint(nbp[(r0 + 8) * PAD + fc + 4]);
            const int bf = kk * 8 + (lane & 3);
#pragma unroll
            for (int j = 0; j < 16; j++) {
                int col = ch * 128 + j * 8 + (lane >> 2);
                uint32_t b0 = __float_as_uint(wn[bf * PAD + col]);
                uint32_t b1 = __float_as_uint(wn[(bf + 4) * PAD + col]);
                mma_tf32(acc[j], a0, a1, a2, a3, b0, b1);
            }
        }

        // af path: exact fp32 FFMA (thread dd, atoms ah*4 .. ah*4+3)
        {
            float war[TF];
#pragma unroll
            for (int f = 0; f < TF; f++) war[f] = wa[f * PAD + dd];
#pragma unroll
            for (int a = 0; a < 4; a++) {
                const float* xp = s + OFF_X + (ah * 4 + a) * F_ + st * TF;
#pragma unroll
                for (int c = 0; c < 4; c++) {
                    float4 xv = *(const float4*)(xp + c * 4);
                    accA[a] = fmaf(xv.x, war[c * 4 + 0],
                              fmaf(xv.y, war[c * 4 + 1],
                              fmaf(xv.z, war[c * 4 + 2],
                              fmaf(xv.w, war[c * 4 + 3], accA[a]))));
                }
            }
        }
        __syncthreads();
    }

    // ---- write C fragments (nf, pre-bias) into smem (reuse nb region) ----
    float* nf = s + OFF_NB;
#pragma unroll
    for (int j = 0; j < 16; j++) {
        int col = ch * 128 + j * 8 + 2 * (lane & 3);
        int r0  = rg * 16 + (lane >> 2);
        *(float2*)(nf + r0 * PAD + col)       = make_float2(acc[j][0], acc[j][1]);
        *(float2*)(nf + (r0 + 8) * PAD + col) = make_float2(acc[j][2], acc[j][3]);
    }
    __syncthreads();

    // ---- epilogue: score -> softmax -> ctx -> LayerNorm, 4 atom-pairs ----
    const float ba_d  = ba[dd];
    const float bn_d  = bn[dd];
    const float wal_d = wal[dd & 63];
    const float bal_s = bal[0];
    const float g_d   = gam[dd];
    const float be_d  = bet[dd];
    const int   wih   = (tid & 255) >> 5;   // warp-in-half
    const int   h     = dd >> 6;            // head
    float* s_red = s + OFF_RED + ah * 128;
    float* s_ln  = s + OFF_LN + ah * 16;
    const float* s_sm = s + OFF_SM;
    const float* s_am = s + OFF_AM;

#pragma unroll
    for (int ag = 0; ag < 4; ag++) {
        const int atom = ah * 4 + ag;
        const float afv = accA[ag] + ba_d;
        float nfr[K_], pp[K_];
#pragma unroll
        for (int k = 0; k < K_; k++) {
            nfr[k] = nf[(atom * 16 + k) * PAD + dd] + bn_d;
            float t = afv + nfr[k];
            t = (t > 0.f) ? t : 0.2f * t;     // leaky relu
            pp[k] = t * wal_d;
        }
#pragma unroll
        for (int off = 16; off; off >>= 1) {
#pragma unroll
            for (int k = 0; k < K_; k++)
                pp[k] += __shfl_xor_sync(0xffffffffu, pp[k], off);
        }
        if (lane == 0) {
#pragma unroll
            for (int k = 0; k < K_; k++) s_red[wih * 16 + k] = pp[k];
        }
        __syncthreads();

        float sc[K_];
        float mx = -3.4e38f;
#pragma unroll
        for (int k = 0; k < K_; k++) {
            sc[k] = s_red[(2 * h) * 16 + k] + s_red[(2 * h + 1) * 16 + k]
                  + bal_s + s_sm[atom * 16 + k];
            mx = fmaxf(mx, sc[k]);
        }
        float ssum = 0.f;
#pragma unroll
        for (int k = 0; k < K_; k++) { sc[k] = __expf(sc[k] - mx); ssum += sc[k]; }
        float inv = 1.f / ssum;
        float ctx = 0.f;
#pragma unroll
        for (int k = 0; k < K_; k++)
            ctx = fmaf(sc[k] * inv * s_am[atom * 16 + k], nfr[k], ctx);

        float s1 = ctx, s2 = ctx * ctx;
#pragma unroll
        for (int off = 16; off; off >>= 1) {
            s1 += __shfl_xor_sync(0xffffffffu, s1, off);
            s2 += __shfl_xor_sync(0xffffffffu, s2, off);
        }
        if (lane == 0) { s_ln[wih] = s1; s_ln[8 + wih] = s2; }
        __syncthreads();
        float S1 = 0.f, S2 = 0.f;
#pragma unroll
        for (int q = 0; q < 8; q++) { S1 += s_ln[q]; S2 += s_ln[8 + q]; }
        float mu  = S1 * (1.f / 256.f);
        float var = S2 * (1.f / 256.f) - mu * mu;
        float o = (ctx - mu) * rsqrtf(var + 1e-5f) * g_d + be_d;
        out[(size_t)(blk * ATOMS + atom) * D_ + dd] = o;
        __syncthreads();
    }
}

extern "C" void kernel_launch(void* const* d_in, const int* in_sizes, int n_in,
                              void* d_out, int out_size)
{
    const float* atom_feat = (const float*)d_in[0];
    const float* nbr_feat  = (const float*)d_in[1];
    const float* smask     = (const float*)d_in[2];
    const float* amask     = (const float*)d_in[3];
    const float* Wa        = (const float*)d_in[4];
    const float* ba        = (const float*)d_in[5];
    const float* Wn        = (const float*)d_in[6];
    const float* bn        = (const float*)d_in[7];
    const float* wal       = (const float*)d_in[8];
    const float* bal       = (const float*)d_in[9];
    const float* gam       = (const float*)d_in[10];
    const float* bet       = (const float*)d_in[11];
    float* out = (float*)d_out;

    cudaFuncSetAttribute(gnn_atom_aggregate_kernel,
                         cudaFuncAttributeMaxDynamicSharedMemorySize,
                         SMEM_FL * (int)sizeof(float));

    gnn_atom_aggregate_kernel<<<(B_ * N_) / ATOMS, THREADS,
                                SMEM_FL * sizeof(float)>>>(
        atom_feat, nbr_feat, smask, amask, Wa, ba, Wn, bn, wal, bal, gam, bet, out);
}